// round 15
// baseline (speedup 1.0000x reference)
#include <cuda_runtime.h>
#include <cuda_fp16.h>
#include <cstdint>

// ---------------------------------------------------------------------------
// GraphConvolution: out = SpMM(COO adj, x @ W) + bias
// Round 14: GEMM grid (1, 391) — both N-tiles looped inside the CTA so the
// second pass over A hits L2 (A DRAM 205 MB -> 102 MB). Gather support loads
// via __ldcg (L2-only; random rows never hit L1). Rest identical to R13.
// ---------------------------------------------------------------------------

#define D 512
#define MAX_NODES 50000
#define MAX_EDGES 400000

__device__ __half g_support[(size_t)MAX_NODES * D];   // 51.2 MB
__device__ int    g_counts[MAX_NODES];                // zero-init; invariant 0
__device__ int    g_offsets[MAX_NODES + 1];
__device__ int    g_cursors[MAX_NODES];
__device__ int    g_blocksums[256];
__device__ int2   g_perm[MAX_EDGES];

struct ForkJoin {
    cudaStream_t side;
    cudaEvent_t  fork_ev, join_ev;
    ForkJoin() {
        cudaStreamCreateWithFlags(&side, cudaStreamNonBlocking);
        cudaEventCreateWithFlags(&fork_ev, cudaEventDisableTiming);
        cudaEventCreateWithFlags(&join_ev, cudaEventDisableTiming);
    }
};
static ForkJoin g_fj;

// ========================= Prep kernels ====================================
__global__ void hist_kernel(const int* __restrict__ rows, int E) {
    int e = blockIdx.x * blockDim.x + threadIdx.x;
    if (e < E) atomicAdd(&g_counts[rows[e]], 1);
}

__global__ __launch_bounds__(512)
void scan1_kernel(int n) {
    __shared__ int ws[16];
    const int tid  = threadIdx.x;
    const int lane = tid & 31;
    const int wid  = tid >> 5;
    const int i = blockIdx.x * 512 + tid;
    const int v = (i < n) ? g_counts[i] : 0;

    int x = v;
    #pragma unroll
    for (int d = 1; d < 32; d <<= 1) {
        int y = __shfl_up_sync(0xffffffffu, x, d);
        if (lane >= d) x += y;
    }
    if (lane == 31) ws[wid] = x;
    __syncthreads();
    if (wid == 0) {
        int w = (lane < 16) ? ws[lane] : 0;
        #pragma unroll
        for (int d = 1; d < 16; d <<= 1) {
            int y = __shfl_up_sync(0xffffffffu, w, d);
            if (lane >= d) w += y;
        }
        if (lane < 16) ws[lane] = w;
    }
    __syncthreads();
    const int excl = (wid ? ws[wid - 1] : 0) + x - v;
    if (i < n) g_offsets[i] = excl;
    if (tid == 511) g_blocksums[blockIdx.x] = ws[15];
}

__global__ __launch_bounds__(128)
void scan2_kernel(int nb) {
    __shared__ int ws[4];
    const int tid  = threadIdx.x;
    const int lane = tid & 31;
    const int wid  = tid >> 5;
    const int v = (tid < nb) ? g_blocksums[tid] : 0;
    int x = v;
    #pragma unroll
    for (int d = 1; d < 32; d <<= 1) {
        int y = __shfl_up_sync(0xffffffffu, x, d);
        if (lane >= d) x += y;
    }
    if (lane == 31) ws[wid] = x;
    __syncthreads();
    if (wid == 0 && lane < 4) {
        int w = ws[lane];
        #pragma unroll
        for (int d = 1; d < 4; d <<= 1) {
            int y = __shfl_up_sync(0x0000000fu, w, d);
            if (lane >= d) w += y;
        }
        ws[lane] = w;
    }
    __syncthreads();
    const int excl = (wid ? ws[wid - 1] : 0) + x - v;
    if (tid < nb) g_blocksums[tid] = excl;
}

__global__ __launch_bounds__(512)
void scan3_kernel(int n, int E) {
    const int i = blockIdx.x * 512 + threadIdx.x;
    if (i < n) {
        const int off = g_offsets[i] + g_blocksums[blockIdx.x];
        g_offsets[i] = off;
        g_cursors[i] = off;
        g_counts[i]  = 0;   // restore invariant for next invocation
    }
    if (i == 0) g_offsets[n] = E;
}

__global__ void place_kernel(const int* __restrict__ rows,
                             const int* __restrict__ cols,
                             const float* __restrict__ vals,
                             int E) {
    int e = blockIdx.x * blockDim.x + threadIdx.x;
    if (e >= E) return;
    int pos = atomicAdd(&g_cursors[rows[e]], 1);
    g_perm[pos] = make_int2(cols[e], __float_as_int(vals[e]));
}

// ---------------------------------------------------------------------------
// FP16 tensor-core GEMM (fp32 accum), double-buffered, CTA tile 128x256x32,
// 512 threads (16 warps 4x4, warp tile 32x64). N-tiles looped INSIDE the CTA
// (grid.x = 1): second pass re-reads A from L2, not DRAM.
// ---------------------------------------------------------------------------
#define BM 128
#define BN 256
#define BK 32
#define KP (BK / 2)
#define ASTRIDE (BM + 8)    // 136; %32==8 -> conflict-free
#define BSTRIDE (BN + 8)    // 264; %32==8 -> conflict-free
#define NTILES (512 / BK)   // 16

__device__ __forceinline__ uint32_t pack_h2(float a, float b) {
    __half2 h = __floats2half2_rn(a, b);
    return *reinterpret_cast<uint32_t*>(&h);
}

__global__ __launch_bounds__(512, 1)
void f16_gemm_kernel(const float* __restrict__ A,
                     const float* __restrict__ B,
                     __half* __restrict__ C,
                     int M) {
    constexpr int N = 512, K = 512;

    __shared__ uint32_t As[2][KP][ASTRIDE];   // 17.4 KB
    __shared__ uint32_t Bs[2][KP][BSTRIDE];   // 33.8 KB

    const int tid  = threadIdx.x;
    const int wid  = tid >> 5;
    const int lane = tid & 31;
    const int g    = lane >> 2;
    const int tg   = lane & 3;

    const int wm = (wid >> 2) * 32;    // 0,32,64,96
    const int wn = (wid & 3) * 64;     // 0,64,128,192

    const int m_base = blockIdx.y * BM;

    float4 a_stage[2];
    float4 b_stage[2][2];

    for (int nt = 0; nt < N / BN; nt++) {
        const int n_base = nt * BN;

        float acc[2][8][4];
        #pragma unroll
        for (int mi = 0; mi < 2; mi++)
            #pragma unroll
            for (int ni = 0; ni < 8; ni++)
                #pragma unroll
                for (int r = 0; r < 4; r++) acc[mi][ni][r] = 0.0f;

        auto load_tile = [&](int k0) {
            #pragma unroll
            for (int j = 0; j < 2; j++) {
                const int f   = tid * 2 + j;
                const int row = f >> 3;
                const int kq  = (f & 7) * 4;
                a_stage[j] = make_float4(0.f, 0.f, 0.f, 0.f);
                if (m_base + row < M)
                    a_stage[j] = *reinterpret_cast<const float4*>(
                                     A + (size_t)(m_base + row) * K + k0 + kq);
            }
            #pragma unroll
            for (int j = 0; j < 2; j++) {
                const int p  = tid * 2 + j;
                const int kp = p >> 6;
                const int nq = (p & 63) * 4;
                b_stage[j][0] = *reinterpret_cast<const float4*>(
                                    B + (size_t)(k0 + 2 * kp) * N + n_base + nq);
                b_stage[j][1] = *reinterpret_cast<const float4*>(
                                    B + (size_t)(k0 + 2 * kp + 1) * N + n_base + nq);
            }
        };

        auto commit_tile = [&](int buf) {
            #pragma unroll
            for (int j = 0; j < 2; j++) {
                const int f   = tid * 2 + j;
                const int row = f >> 3;
                const int kq  = (f & 7) * 4;
                const int kp  = kq >> 1;
                As[buf][kp    ][row] = pack_h2(a_stage[j].x, a_stage[j].y);
                As[buf][kp + 1][row] = pack_h2(a_stage[j].z, a_stage[j].w);
            }
            #pragma unroll
            for (int j = 0; j < 2; j++) {
                const int p  = tid * 2 + j;
                const int kp = p >> 6;
                const int nq = (p & 63) * 4;
                uint4 t;
                t.x = pack_h2(b_stage[j][0].x, b_stage[j][1].x);
                t.y = pack_h2(b_stage[j][0].y, b_stage[j][1].y);
                t.z = pack_h2(b_stage[j][0].z, b_stage[j][1].z);
                t.w = pack_h2(b_stage[j][0].w, b_stage[j][1].w);
                *reinterpret_cast<uint4*>(&Bs[buf][kp][nq]) = t;
            }
        };

        // NOTE: writing buffer 0 here is safe even while trailing warps of
        // the previous n-tile compute on buffer 1: buffer 0's last readers
        // were fenced by the final k-iteration's top __syncthreads().
        load_tile(0);
        commit_tile(0);

        for (int c = 0; c < NTILES; c++) {
            const int buf = c & 1;
            __syncthreads();

            if (c + 1 < NTILES) load_tile((c + 1) * BK);

            #pragma unroll
            for (int ks = 0; ks < KP; ks += 8) {
                uint32_t a[2][4], b[8][2];
                #pragma unroll
                for (int mi = 0; mi < 2; mi++) {
                    const int m0 = wm + mi * 16;
                    a[mi][0] = As[buf][ks + tg    ][m0 + g    ];
                    a[mi][1] = As[buf][ks + tg    ][m0 + g + 8];
                    a[mi][2] = As[buf][ks + tg + 4][m0 + g    ];
                    a[mi][3] = As[buf][ks + tg + 4][m0 + g + 8];
                }
                #pragma unroll
                for (int ni = 0; ni < 8; ni++) {
                    const int n0 = wn + ni * 8;
                    b[ni][0] = Bs[buf][ks + tg    ][n0 + g];
                    b[ni][1] = Bs[buf][ks + tg + 4][n0 + g];
                }
                #pragma unroll
                for (int mi = 0; mi < 2; mi++)
                    #pragma unroll
                    for (int ni = 0; ni < 8; ni++) {
                        asm volatile(
                            "mma.sync.aligned.m16n8k16.row.col.f32.f16.f16.f32 "
                            "{%0,%1,%2,%3}, {%4,%5,%6,%7}, {%8,%9}, {%0,%1,%2,%3};"
                            : "+f"(acc[mi][ni][0]), "+f"(acc[mi][ni][1]),
                              "+f"(acc[mi][ni][2]), "+f"(acc[mi][ni][3])
                            : "r"(a[mi][0]), "r"(a[mi][1]), "r"(a[mi][2]), "r"(a[mi][3]),
                              "r"(b[ni][0]), "r"(b[ni][1]));
                    }
            }

            if (c + 1 < NTILES) commit_tile(buf ^ 1);
        }

        // epilogue for this n-tile (register-only; no smem hazard)
        #pragma unroll
        for (int mi = 0; mi < 2; mi++) {
            const int row0 = m_base + wm + mi * 16 + g;
            const int row1 = row0 + 8;
            #pragma unroll
            for (int ni = 0; ni < 8; ni++) {
                const int col = n_base + wn + ni * 8 + 2 * tg;
                if (row0 < M) {
                    __half2 h = __floats2half2_rn(acc[mi][ni][0], acc[mi][ni][1]);
                    *reinterpret_cast<__half2*>(C + (size_t)row0 * N + col) = h;
                }
                if (row1 < M) {
                    __half2 h = __floats2half2_rn(acc[mi][ni][2], acc[mi][ni][3]);
                    *reinterpret_cast<__half2*>(C + (size_t)row1 * N + col) = h;
                }
            }
        }
    }
}

// ---------------------------------------------------------------------------
// Row-gather: 2 warps/row, uint4 LDG.128 via __ldcg (L2-only). (else R12)
// ---------------------------------------------------------------------------
__global__ __launch_bounds__(256)
void row_gather_kernel(const float* __restrict__ bias,
                       float* __restrict__ out,
                       int n_rows) {
    const int gw   = (blockIdx.x * blockDim.x + threadIdx.x) >> 5;
    const int lane = threadIdx.x & 31;
    const int row  = gw >> 1;
    const int part = gw & 1;
    if (row >= n_rows) return;

    const int s = g_offsets[row];
    const int e = g_offsets[row + 1];
    const int fo = part * 32 + lane;

    float acc[8];
    #pragma unroll
    for (int q = 0; q < 8; q++) acc[q] = 0.0f;

    int i = s;
    for (; i + 1 < e; i += 2) {
        const int2 cv0 = __ldcs(&g_perm[i]);
        const int2 cv1 = __ldcs(&g_perm[i + 1]);
        const uint4 m0 = __ldcg(reinterpret_cast<const uint4*>(
                             g_support + (size_t)cv0.x * D) + fo);
        const uint4 m1 = __ldcg(reinterpret_cast<const uint4*>(
                             g_support + (size_t)cv1.x * D) + fo);
        const float v0 = __int_as_float(cv0.y);
        const float v1 = __int_as_float(cv1.y);

        const float2 p00 = __half22float2(*reinterpret_cast<const __half2*>(&m0.x));
        const float2 p01 = __half22float2(*reinterpret_cast<const __half2*>(&m0.y));
        const float2 p02 = __half22float2(*reinterpret_cast<const __half2*>(&m0.z));
        const float2 p03 = __half22float2(*reinterpret_cast<const __half2*>(&m0.w));
        const float2 p10 = __half22float2(*reinterpret_cast<const __half2*>(&m1.x));
        const float2 p11 = __half22float2(*reinterpret_cast<const __half2*>(&m1.y));
        const float2 p12 = __half22float2(*reinterpret_cast<const __half2*>(&m1.z));
        const float2 p13 = __half22float2(*reinterpret_cast<const __half2*>(&m1.w));

        acc[0] += v0 * p00.x + v1 * p10.x;
        acc[1] += v0 * p00.y + v1 * p10.y;
        acc[2] += v0 * p01.x + v1 * p11.x;
        acc[3] += v0 * p01.y + v1 * p11.y;
        acc[4] += v0 * p02.x + v1 * p12.x;
        acc[5] += v0 * p02.y + v1 * p12.y;
        acc[6] += v0 * p03.x + v1 * p13.x;
        acc[7] += v0 * p03.y + v1 * p13.y;
    }
    for (; i < e; i++) {
        const int2 cv = __ldcs(&g_perm[i]);
        const float v = __int_as_float(cv.y);
        const uint4 m = __ldcg(reinterpret_cast<const uint4*>(
                            g_support + (size_t)cv.x * D) + fo);
        const float2 p0 = __half22float2(*reinterpret_cast<const __half2*>(&m.x));
        const float2 p1 = __half22float2(*reinterpret_cast<const __half2*>(&m.y));
        const float2 p2 = __half22float2(*reinterpret_cast<const __half2*>(&m.z));
        const float2 p3 = __half22float2(*reinterpret_cast<const __half2*>(&m.w));
        acc[0] += v * p0.x;
        acc[1] += v * p0.y;
        acc[2] += v * p1.x;
        acc[3] += v * p1.y;
        acc[4] += v * p2.x;
        acc[5] += v * p2.y;
        acc[6] += v * p3.x;
        acc[7] += v * p3.y;
    }

    const float4 b0 = __ldg(reinterpret_cast<const float4*>(bias) + 2 * fo);
    const float4 b1 = __ldg(reinterpret_cast<const float4*>(bias) + 2 * fo + 1);
    float4* op = reinterpret_cast<float4*>(out + (size_t)row * D) + 2 * fo;
    __stcs(op,     make_float4(acc[0] + b0.x, acc[1] + b0.y,
                               acc[2] + b0.z, acc[3] + b0.w));
    __stcs(op + 1, make_float4(acc[4] + b1.x, acc[5] + b1.y,
                               acc[6] + b1.z, acc[7] + b1.w));
}

// ========================= Launch ==========================================
extern "C" void kernel_launch(void* const* d_in, const int* in_sizes, int n_in,
                              void* d_out, int out_size) {
    const float* x        = (const float*)d_in[0];
    const int*   adj_rows = (const int*)  d_in[1];
    const int*   adj_cols = (const int*)  d_in[2];
    const float* adj_vals = (const float*)d_in[3];
    const float* weight   = (const float*)d_in[4];
    const float* bias     = (const float*)d_in[5];
    float* out = (float*)d_out;

    const int M = in_sizes[0] / D;   // N_NODES
    const int E = in_sizes[1];       // N_EDGES

    // ---- fork: prep chain on side stream, GEMM on main stream ----
    cudaEventRecord(g_fj.fork_ev, 0);
    cudaStreamWaitEvent(g_fj.side, g_fj.fork_ev, 0);

    hist_kernel<<<(E + 255) / 256, 256, 0, g_fj.side>>>(adj_rows, E);
    const int nb = (M + 511) / 512;
    scan1_kernel<<<nb, 512, 0, g_fj.side>>>(M);
    scan2_kernel<<<1, 128, 0, g_fj.side>>>(nb);
    scan3_kernel<<<nb, 512, 0, g_fj.side>>>(M, E);
    place_kernel<<<(E + 255) / 256, 256, 0, g_fj.side>>>(adj_rows, adj_cols,
                                                         adj_vals, E);
    cudaEventRecord(g_fj.join_ev, g_fj.side);

    // GEMM on the main (capture) stream, concurrent with prep
    {
        __half* support;
        cudaGetSymbolAddress((void**)&support, g_support);
        dim3 grid(1, (M + BM - 1) / BM);   // (1, 391): n-tiles inside CTA
        f16_gemm_kernel<<<grid, 512>>>(x, weight, support, M);
    }

    // ---- join: gather needs both GEMM output and CSR ----
    cudaStreamWaitEvent(0, g_fj.join_ev, 0);
    {
        int total_warps = 2 * M;
        int blocks = (total_warps + 7) / 8;
        row_gather_kernel<<<blocks, 256>>>(bias, out, M);
    }
}

// round 16
// speedup vs baseline: 1.0044x; 1.0044x over previous
#include <cuda_runtime.h>
#include <cuda_fp16.h>
#include <cstdint>

// ---------------------------------------------------------------------------
// GraphConvolution: out = SpMM(COO adj, x @ W) + bias
// Round 15: edges counting-sorted by (row, col-bucket) with 4 column buckets
// (key = row*4 + col/12500). Gather reads each bucket's support region while
// it is L2-resident (instantaneous footprint ~13-26 MB vs 51 MB), cutting the
// gather's DRAM re-fetch of support. Gather loop itself unchanged (a row's
// edges remain contiguous). GEMM/topology identical to R14.
// ---------------------------------------------------------------------------

#define D 512
#define MAX_NODES 50000
#define MAX_EDGES 400000
#define NB 4                               // column buckets
#define NKEYS (NB * MAX_NODES)             // 200000

__device__ __half g_support[(size_t)MAX_NODES * D];   // 51.2 MB
__device__ int    g_counts[NKEYS];                    // zero-init; invariant 0
__device__ int    g_offsets[NKEYS + 1];
__device__ int    g_cursors[NKEYS];
__device__ int    g_blocksums[512];
__device__ int2   g_perm[MAX_EDGES];

struct ForkJoin {
    cudaStream_t side;
    cudaEvent_t  fork_ev, join_ev;
    ForkJoin() {
        cudaStreamCreateWithFlags(&side, cudaStreamNonBlocking);
        cudaEventCreateWithFlags(&fork_ev, cudaEventDisableTiming);
        cudaEventCreateWithFlags(&join_ev, cudaEventDisableTiming);
    }
};
static ForkJoin g_fj;

// ========================= Prep kernels ====================================
__global__ void hist_kernel(const int* __restrict__ rows,
                            const int* __restrict__ cols,
                            int E, int bdiv) {
    int e = blockIdx.x * blockDim.x + threadIdx.x;
    if (e >= E) return;
    const int key = rows[e] * NB + cols[e] / bdiv;
    atomicAdd(&g_counts[key], 1);
}

__global__ __launch_bounds__(512)
void scan1_kernel(int n) {
    __shared__ int ws[16];
    const int tid  = threadIdx.x;
    const int lane = tid & 31;
    const int wid  = tid >> 5;
    const int i = blockIdx.x * 512 + tid;
    const int v = (i < n) ? g_counts[i] : 0;

    int x = v;
    #pragma unroll
    for (int d = 1; d < 32; d <<= 1) {
        int y = __shfl_up_sync(0xffffffffu, x, d);
        if (lane >= d) x += y;
    }
    if (lane == 31) ws[wid] = x;
    __syncthreads();
    if (wid == 0) {
        int w = (lane < 16) ? ws[lane] : 0;
        #pragma unroll
        for (int d = 1; d < 16; d <<= 1) {
            int y = __shfl_up_sync(0xffffffffu, w, d);
            if (lane >= d) w += y;
        }
        if (lane < 16) ws[lane] = w;
    }
    __syncthreads();
    const int excl = (wid ? ws[wid - 1] : 0) + x - v;
    if (i < n) g_offsets[i] = excl;
    if (tid == 511) g_blocksums[blockIdx.x] = ws[15];
}

// scan of block sums: single block, 512 threads, nb <= 512
__global__ __launch_bounds__(512)
void scan2_kernel(int nb) {
    __shared__ int ws[16];
    const int tid  = threadIdx.x;
    const int lane = tid & 31;
    const int wid  = tid >> 5;
    const int v = (tid < nb) ? g_blocksums[tid] : 0;

    int x = v;
    #pragma unroll
    for (int d = 1; d < 32; d <<= 1) {
        int y = __shfl_up_sync(0xffffffffu, x, d);
        if (lane >= d) x += y;
    }
    if (lane == 31) ws[wid] = x;
    __syncthreads();
    if (wid == 0) {
        int w = (lane < 16) ? ws[lane] : 0;
        #pragma unroll
        for (int d = 1; d < 16; d <<= 1) {
            int y = __shfl_up_sync(0xffffffffu, w, d);
            if (lane >= d) w += y;
        }
        if (lane < 16) ws[lane] = w;
    }
    __syncthreads();
    const int excl = (wid ? ws[wid - 1] : 0) + x - v;
    if (tid < nb) g_blocksums[tid] = excl;
}

__global__ __launch_bounds__(512)
void scan3_kernel(int n, int E) {
    const int i = blockIdx.x * 512 + threadIdx.x;
    if (i < n) {
        const int off = g_offsets[i] + g_blocksums[blockIdx.x];
        g_offsets[i] = off;
        g_cursors[i] = off;
        g_counts[i]  = 0;   // restore invariant for next invocation
    }
    if (i == 0) g_offsets[n] = E;
}

__global__ void place_kernel(const int* __restrict__ rows,
                             const int* __restrict__ cols,
                             const float* __restrict__ vals,
                             int E, int bdiv) {
    int e = blockIdx.x * blockDim.x + threadIdx.x;
    if (e >= E) return;
    const int c = cols[e];
    const int key = rows[e] * NB + c / bdiv;
    int pos = atomicAdd(&g_cursors[key], 1);
    g_perm[pos] = make_int2(c, __float_as_int(vals[e]));
}

// ---------------------------------------------------------------------------
// FP16 tensor-core GEMM (fp32 accum), double-buffered, CTA tile 128x256x32,
// 512 threads (16 warps 4x4, warp tile 32x64). N-tiles looped inside the CTA.
// (R14 exact)
// ---------------------------------------------------------------------------
#define BM 128
#define BN 256
#define BK 32
#define KP (BK / 2)
#define ASTRIDE (BM + 8)
#define BSTRIDE (BN + 8)
#define NTILES (512 / BK)

__device__ __forceinline__ uint32_t pack_h2(float a, float b) {
    __half2 h = __floats2half2_rn(a, b);
    return *reinterpret_cast<uint32_t*>(&h);
}

__global__ __launch_bounds__(512, 1)
void f16_gemm_kernel(const float* __restrict__ A,
                     const float* __restrict__ B,
                     __half* __restrict__ C,
                     int M) {
    constexpr int N = 512, K = 512;

    __shared__ uint32_t As[2][KP][ASTRIDE];
    __shared__ uint32_t Bs[2][KP][BSTRIDE];

    const int tid  = threadIdx.x;
    const int wid  = tid >> 5;
    const int lane = tid & 31;
    const int g    = lane >> 2;
    const int tg   = lane & 3;

    const int wm = (wid >> 2) * 32;
    const int wn = (wid & 3) * 64;

    const int m_base = blockIdx.y * BM;

    float4 a_stage[2];
    float4 b_stage[2][2];

    for (int nt = 0; nt < N / BN; nt++) {
        const int n_base = nt * BN;

        float acc[2][8][4];
        #pragma unroll
        for (int mi = 0; mi < 2; mi++)
            #pragma unroll
            for (int ni = 0; ni < 8; ni++)
                #pragma unroll
                for (int r = 0; r < 4; r++) acc[mi][ni][r] = 0.0f;

        auto load_tile = [&](int k0) {
            #pragma unroll
            for (int j = 0; j < 2; j++) {
                const int f   = tid * 2 + j;
                const int row = f >> 3;
                const int kq  = (f & 7) * 4;
                a_stage[j] = make_float4(0.f, 0.f, 0.f, 0.f);
                if (m_base + row < M)
                    a_stage[j] = *reinterpret_cast<const float4*>(
                                     A + (size_t)(m_base + row) * K + k0 + kq);
            }
            #pragma unroll
            for (int j = 0; j < 2; j++) {
                const int p  = tid * 2 + j;
                const int kp = p >> 6;
                const int nq = (p & 63) * 4;
                b_stage[j][0] = *reinterpret_cast<const float4*>(
                                    B + (size_t)(k0 + 2 * kp) * N + n_base + nq);
                b_stage[j][1] = *reinterpret_cast<const float4*>(
                                    B + (size_t)(k0 + 2 * kp + 1) * N + n_base + nq);
            }
        };

        auto commit_tile = [&](int buf) {
            #pragma unroll
            for (int j = 0; j < 2; j++) {
                const int f   = tid * 2 + j;
                const int row = f >> 3;
                const int kq  = (f & 7) * 4;
                const int kp  = kq >> 1;
                As[buf][kp    ][row] = pack_h2(a_stage[j].x, a_stage[j].y);
                As[buf][kp + 1][row] = pack_h2(a_stage[j].z, a_stage[j].w);
            }
            #pragma unroll
            for (int j = 0; j < 2; j++) {
                const int p  = tid * 2 + j;
                const int kp = p >> 6;
                const int nq = (p & 63) * 4;
                uint4 t;
                t.x = pack_h2(b_stage[j][0].x, b_stage[j][1].x);
                t.y = pack_h2(b_stage[j][0].y, b_stage[j][1].y);
                t.z = pack_h2(b_stage[j][0].z, b_stage[j][1].z);
                t.w = pack_h2(b_stage[j][0].w, b_stage[j][1].w);
                *reinterpret_cast<uint4*>(&Bs[buf][kp][nq]) = t;
            }
        };

        load_tile(0);
        commit_tile(0);

        for (int c = 0; c < NTILES; c++) {
            const int buf = c & 1;
            __syncthreads();

            if (c + 1 < NTILES) load_tile((c + 1) * BK);

            #pragma unroll
            for (int ks = 0; ks < KP; ks += 8) {
                uint32_t a[2][4], b[8][2];
                #pragma unroll
                for (int mi = 0; mi < 2; mi++) {
                    const int m0 = wm + mi * 16;
                    a[mi][0] = As[buf][ks + tg    ][m0 + g    ];
                    a[mi][1] = As[buf][ks + tg    ][m0 + g + 8];
                    a[mi][2] = As[buf][ks + tg + 4][m0 + g    ];
                    a[mi][3] = As[buf][ks + tg + 4][m0 + g + 8];
                }
                #pragma unroll
                for (int ni = 0; ni < 8; ni++) {
                    const int n0 = wn + ni * 8;
                    b[ni][0] = Bs[buf][ks + tg    ][n0 + g];
                    b[ni][1] = Bs[buf][ks + tg + 4][n0 + g];
                }
                #pragma unroll
                for (int mi = 0; mi < 2; mi++)
                    #pragma unroll
                    for (int ni = 0; ni < 8; ni++) {
                        asm volatile(
                            "mma.sync.aligned.m16n8k16.row.col.f32.f16.f16.f32 "
                            "{%0,%1,%2,%3}, {%4,%5,%6,%7}, {%8,%9}, {%0,%1,%2,%3};"
                            : "+f"(acc[mi][ni][0]), "+f"(acc[mi][ni][1]),
                              "+f"(acc[mi][ni][2]), "+f"(acc[mi][ni][3])
                            : "r"(a[mi][0]), "r"(a[mi][1]), "r"(a[mi][2]), "r"(a[mi][3]),
                              "r"(b[ni][0]), "r"(b[ni][1]));
                    }
            }

            if (c + 1 < NTILES) commit_tile(buf ^ 1);
        }

        #pragma unroll
        for (int mi = 0; mi < 2; mi++) {
            const int row0 = m_base + wm + mi * 16 + g;
            const int row1 = row0 + 8;
            #pragma unroll
            for (int ni = 0; ni < 8; ni++) {
                const int col = n_base + wn + ni * 8 + 2 * tg;
                if (row0 < M) {
                    __half2 h = __floats2half2_rn(acc[mi][ni][0], acc[mi][ni][1]);
                    *reinterpret_cast<__half2*>(C + (size_t)row0 * N + col) = h;
                }
                if (row1 < M) {
                    __half2 h = __floats2half2_rn(acc[mi][ni][2], acc[mi][ni][3]);
                    *reinterpret_cast<__half2*>(C + (size_t)row1 * N + col) = h;
                }
            }
        }
    }
}

// ---------------------------------------------------------------------------
// Row-gather: 2 warps/row, uint4 LDG.128 via __ldcg. Row r's edges are
// contiguous at [offsets[r*NB], offsets[r*NB+NB]) in column-bucket order.
// ---------------------------------------------------------------------------
__global__ __launch_bounds__(256)
void row_gather_kernel(const float* __restrict__ bias,
                       float* __restrict__ out,
                       int n_rows) {
    const int gw   = (blockIdx.x * blockDim.x + threadIdx.x) >> 5;
    const int lane = threadIdx.x & 31;
    const int row  = gw >> 1;
    const int part = gw & 1;
    if (row >= n_rows) return;

    const int s = g_offsets[row * NB];
    const int e = g_offsets[row * NB + NB];
    const int fo = part * 32 + lane;

    float acc[8];
    #pragma unroll
    for (int q = 0; q < 8; q++) acc[q] = 0.0f;

    int i = s;
    for (; i + 1 < e; i += 2) {
        const int2 cv0 = __ldcs(&g_perm[i]);
        const int2 cv1 = __ldcs(&g_perm[i + 1]);
        const uint4 m0 = __ldcg(reinterpret_cast<const uint4*>(
                             g_support + (size_t)cv0.x * D) + fo);
        const uint4 m1 = __ldcg(reinterpret_cast<const uint4*>(
                             g_support + (size_t)cv1.x * D) + fo);
        const float v0 = __int_as_float(cv0.y);
        const float v1 = __int_as_float(cv1.y);

        const float2 p00 = __half22float2(*reinterpret_cast<const __half2*>(&m0.x));
        const float2 p01 = __half22float2(*reinterpret_cast<const __half2*>(&m0.y));
        const float2 p02 = __half22float2(*reinterpret_cast<const __half2*>(&m0.z));
        const float2 p03 = __half22float2(*reinterpret_cast<const __half2*>(&m0.w));
        const float2 p10 = __half22float2(*reinterpret_cast<const __half2*>(&m1.x));
        const float2 p11 = __half22float2(*reinterpret_cast<const __half2*>(&m1.y));
        const float2 p12 = __half22float2(*reinterpret_cast<const __half2*>(&m1.z));
        const float2 p13 = __half22float2(*reinterpret_cast<const __half2*>(&m1.w));

        acc[0] += v0 * p00.x + v1 * p10.x;
        acc[1] += v0 * p00.y + v1 * p10.y;
        acc[2] += v0 * p01.x + v1 * p11.x;
        acc[3] += v0 * p01.y + v1 * p11.y;
        acc[4] += v0 * p02.x + v1 * p12.x;
        acc[5] += v0 * p02.y + v1 * p12.y;
        acc[6] += v0 * p03.x + v1 * p13.x;
        acc[7] += v0 * p03.y + v1 * p13.y;
    }
    for (; i < e; i++) {
        const int2 cv = __ldcs(&g_perm[i]);
        const float v = __int_as_float(cv.y);
        const uint4 m = __ldcg(reinterpret_cast<const uint4*>(
                            g_support + (size_t)cv.x * D) + fo);
        const float2 p0 = __half22float2(*reinterpret_cast<const __half2*>(&m.x));
        const float2 p1 = __half22float2(*reinterpret_cast<const __half2*>(&m.y));
        const float2 p2 = __half22float2(*reinterpret_cast<const __half2*>(&m.z));
        const float2 p3 = __half22float2(*reinterpret_cast<const __half2*>(&m.w));
        acc[0] += v * p0.x;
        acc[1] += v * p0.y;
        acc[2] += v * p1.x;
        acc[3] += v * p1.y;
        acc[4] += v * p2.x;
        acc[5] += v * p2.y;
        acc[6] += v * p3.x;
        acc[7] += v * p3.y;
    }

    const float4 b0 = __ldg(reinterpret_cast<const float4*>(bias) + 2 * fo);
    const float4 b1 = __ldg(reinterpret_cast<const float4*>(bias) + 2 * fo + 1);
    float4* op = reinterpret_cast<float4*>(out + (size_t)row * D) + 2 * fo;
    __stcs(op,     make_float4(acc[0] + b0.x, acc[1] + b0.y,
                               acc[2] + b0.z, acc[3] + b0.w));
    __stcs(op + 1, make_float4(acc[4] + b1.x, acc[5] + b1.y,
                               acc[6] + b1.z, acc[7] + b1.w));
}

// ========================= Launch ==========================================
extern "C" void kernel_launch(void* const* d_in, const int* in_sizes, int n_in,
                              void* d_out, int out_size) {
    const float* x        = (const float*)d_in[0];
    const int*   adj_rows = (const int*)  d_in[1];
    const int*   adj_cols = (const int*)  d_in[2];
    const float* adj_vals = (const float*)d_in[3];
    const float* weight   = (const float*)d_in[4];
    const float* bias     = (const float*)d_in[5];
    float* out = (float*)d_out;

    const int M = in_sizes[0] / D;   // N_NODES
    const int E = in_sizes[1];       // N_EDGES
    const int bdiv = (M + NB - 1) / NB;   // 12500
    const int n2 = M * NB;                // 200000 keys

    // ---- fork: prep chain on side stream, GEMM on main stream ----
    cudaEventRecord(g_fj.fork_ev, 0);
    cudaStreamWaitEvent(g_fj.side, g_fj.fork_ev, 0);

    hist_kernel<<<(E + 255) / 256, 256, 0, g_fj.side>>>(adj_rows, adj_cols,
                                                        E, bdiv);
    const int nb = (n2 + 511) / 512;      // 391 <= 512
    scan1_kernel<<<nb, 512, 0, g_fj.side>>>(n2);
    scan2_kernel<<<1, 512, 0, g_fj.side>>>(nb);
    scan3_kernel<<<nb, 512, 0, g_fj.side>>>(n2, E);
    place_kernel<<<(E + 255) / 256, 256, 0, g_fj.side>>>(adj_rows, adj_cols,
                                                         adj_vals, E, bdiv);
    cudaEventRecord(g_fj.join_ev, g_fj.side);

    // GEMM on the main (capture) stream, concurrent with prep
    {
        __half* support;
        cudaGetSymbolAddress((void**)&support, g_support);
        dim3 grid(1, (M + BM - 1) / BM);
        f16_gemm_kernel<<<grid, 512>>>(x, weight, support, M);
    }

    // ---- join: gather needs both GEMM output and CSR ----
    cudaStreamWaitEvent(0, g_fj.join_ev, 0);
    {
        int total_warps = 2 * M;
        int blocks = (total_warps + 7) / 8;
        row_gather_kernel<<<blocks, 256>>>(bias, out, M);
    }
}